// round 15
// baseline (speedup 1.0000x reference)
#include <cuda_runtime.h>
#include <cuda_fp16.h>
#include <math.h>
#include <stdint.h>

// Problem constants
#define TOK   4096      // B*S
#define DIM   1024      // D == R
#define SEQ   2048
#define NBATCH 2
#define NH    8
#define DHEAD 128
#define NEXP  8
#define NPROC 32
#define TOPK  3
#define KTOT  8192      // NEXP * DIM
#define WSZ   ((size_t)DIM * KTOT)   // elements per weight slot
#define ASZ   ((size_t)TOK * DIM)

// GEMM tiling: 128x128xBK128, 512 threads, 2 stages, fp16 2-pass
#define BK      128
#define NCHUNK  (KTOT / BK)           // 64
#define PAD     136                   // smem row stride in fp16 halves (272B, 16B-aligned)
#define MAT_BYTES   (128 * PAD * 2)   // 34816 per matrix
#define STAGE_BYTES (3 * MAT_BYTES)   // A, Bhi, Blo = 104448
#define NSTAGE  2
#define SMEM_GEMM_BYTES (NSTAGE * STAGE_BYTES)   // 208896

// Attention smem layout (dynamic): Ks[32][132] | Vs[32][132] | qs[32][128]
#define KS_STRIDE 132
#define QS_STRIDE 128
#define ATTN_KS_OFF 0
#define ATTN_VS_OFF (32 * KS_STRIDE)
#define ATTN_QS_OFF (2 * 32 * KS_STRIDE)
#define SMEM_ATTN_BYTES ((2 * 32 * KS_STRIDE + 32 * QS_STRIDE) * 4)   // 50176

// Weight slots: 0=Wq_in 1=Wk_in 2=Wv_in 3=Wq_out 4=Wk_out 5=Wv_out 6=Wo_in 7=Wo_out
// ---------------------------------------------------------------------------
// Scratch (device globals — no runtime allocation allowed)
// ---------------------------------------------------------------------------
__device__ float g_h  [3 * TOK * DIM];
__device__ float g_Q  [TOK * DIM];
__device__ float g_Kc [TOK * DIM];
__device__ float g_V  [TOK * DIM];
__device__ float g_O  [TOK * DIM];
__device__ float g_inw [TOK * NEXP];
__device__ float g_outw[TOK * NEXP];
__device__ int   g_pidx[TOK * TOPK];
__device__ __half g_whi[8 * DIM * KTOT];   // weightT hi, 8 slots [N=1024, K=8192]
__device__ __half g_wlo[8 * DIM * KTOT];
__device__ __half g_xh [TOK * DIM];        // activation fp16 (x / O)
__device__ __half g_hh [3 * TOK * DIM];    // householder output fp16

// ---------------------------------------------------------------------------
// Portable tensor-core helpers (sm_80+ PTX; no 'a'-suffix features)
// ---------------------------------------------------------------------------
#define LDSM4(r0, r1, r2, r3, addr) \
    asm volatile("ldmatrix.sync.aligned.m8n8.x4.shared.b16 {%0,%1,%2,%3}, [%4];" \
                 : "=r"(r0), "=r"(r1), "=r"(r2), "=r"(r3) : "r"(addr))

__device__ __forceinline__ void mma_f16(float* c, const uint32_t* a, const uint32_t* b) {
    asm volatile(
        "mma.sync.aligned.m16n8k16.row.col.f32.f16.f16.f32 "
        "{%0,%1,%2,%3}, {%4,%5,%6,%7}, {%8,%9}, {%0,%1,%2,%3};"
        : "+f"(c[0]), "+f"(c[1]), "+f"(c[2]), "+f"(c[3])
        : "r"(a[0]), "r"(a[1]), "r"(a[2]), "r"(a[3]), "r"(b[0]), "r"(b[1]));
}

__device__ __forceinline__ void cp16(uint32_t saddr, const void* gaddr) {
    asm volatile("cp.async.cg.shared.global [%0], [%1], 16;" :: "r"(saddr), "l"(gaddr));
}
__device__ __forceinline__ void cp_commit() {
    asm volatile("cp.async.commit_group;" ::: "memory");
}
template <int N>
__device__ __forceinline__ void cp_wait() {
    asm volatile("cp.async.wait_group %0;" :: "n"(N) : "memory");
}

__device__ __forceinline__ void split_f16(float v, __half& hi, __half& lo) {
    hi = __float2half_rn(v);
    lo = __float2half_rn(v - __half2float(hi));
}

// ---------------------------------------------------------------------------
// Weight prep (8-slot batched): W_z[KTOT, DIM] fp32 -> fp16 hi/lo [DIM, KTOT]
// ---------------------------------------------------------------------------
__global__ void prep_w_kernel(const float* __restrict__ W0,
                              const float* __restrict__ W1,
                              const float* __restrict__ W2,
                              const float* __restrict__ W3,
                              const float* __restrict__ W4,
                              const float* __restrict__ W5,
                              const float* __restrict__ W6,
                              const float* __restrict__ W7,
                              __half* __restrict__ Whi,
                              __half* __restrict__ Wlo)
{
    int z = blockIdx.z;
    const float* W = (z == 0) ? W0 : (z == 1) ? W1 : (z == 2) ? W2 : (z == 3) ? W3
                   : (z == 4) ? W4 : (z == 5) ? W5 : (z == 6) ? W6 : W7;
    __half* whi = Whi + (size_t)z * WSZ;
    __half* wlo = Wlo + (size_t)z * WSZ;

    __shared__ float ts[32][33];
    int k0 = blockIdx.y * 32, n0 = blockIdx.x * 32;
    int tx = threadIdx.x & 31, ty = threadIdx.x >> 5;   // 32 x 8
    #pragma unroll
    for (int r = 0; r < 4; r++) {
        int k = ty + r * 8;
        ts[k][tx] = W[(size_t)(k0 + k) * DIM + n0 + tx];
    }
    __syncthreads();
    #pragma unroll
    for (int r = 0; r < 4; r++) {
        int n = ty + r * 8;
        float v = ts[tx][n];                      // W[k0+tx][n0+n]
        __half h, l;
        split_f16(v, h, l);
        size_t o = (size_t)(n0 + n) * KTOT + k0 + tx;
        whi[o] = h;
        wlo[o] = l;
    }
}

// ---------------------------------------------------------------------------
// Activation convert: fp32 [TOK,DIM] -> fp16
// ---------------------------------------------------------------------------
__global__ void split_kernel(const float* __restrict__ src,
                             __half* __restrict__ dst)
{
    int i = (blockIdx.x * 256 + threadIdx.x) * 4;
    float4 v = *(const float4*)(src + i);
    __half h[4];
    h[0] = __float2half_rn(v.x);
    h[1] = __float2half_rn(v.y);
    h[2] = __float2half_rn(v.z);
    h[3] = __float2half_rn(v.w);
    *(uint64_t*)(dst + i) = *(uint64_t*)h;
}

// ---------------------------------------------------------------------------
// Tensor-core mixture GEMM via mma.sync (fp16 A + hi/lo B, 2 passes, fp32 acc).
// z-batched: blockIdx.z selects A (via aStride), weight slot, and output.
// 512 threads / 16 warps: 4(M) x 4(N) warp grid, 32x32 warp tile,
// BK=128 chunks (64 barriers), 2-stage cp.async pipeline.
// ---------------------------------------------------------------------------
__global__ __launch_bounds__(512)
void circuit_gemm_tc(const __half* __restrict__ A,      // base, + z*aStride
                     size_t aStride,
                     const __half* __restrict__ WhiB,   // slot base (z-indexed)
                     const __half* __restrict__ WloB,
                     const float* __restrict__ wgt,     // [TOK, NEXP]
                     float* __restrict__ o0,
                     float* __restrict__ o1,
                     float* __restrict__ o2)
{
    extern __shared__ char smem[];
    __shared__ float swgt[128 * NEXP];
    const uint32_t sb = (uint32_t)__cvta_generic_to_shared(smem);
    int tid = threadIdx.x, lane = tid & 31, wid = tid >> 5;
    int bm = blockIdx.y * 128, bn = blockIdx.x * 128;
    int z  = blockIdx.z;
    const __half* AZ  = A + (size_t)z * aStride;
    const __half* Whi = WhiB + (size_t)z * WSZ;
    const __half* Wlo = WloB + (size_t)z * WSZ;
    float* out = (z == 0) ? o0 : (z == 1) ? o1 : o2;

    // ---- loader role: 4 threads per row, 32-halves (64B) quarter each ----
    int r  = tid >> 2;                 // 0..127
    int kq = (tid & 3) * 32;           // k quarter (halves)
    const __half* ap   = AZ  + (size_t)(bm + r) * DIM + kq;
    const __half* bhip = Whi + (size_t)(bn + r) * KTOT + kq;
    const __half* blop = Wlo + (size_t)(bn + r) * KTOT + kq;
    const uint32_t rowoff = (uint32_t)(r * PAD + kq) * 2;

    auto load_chunk = [&](int c) {
        uint32_t st = sb + (uint32_t)(c & 1) * STAGE_BYTES;
        int k0 = c * BK;
        int d0 = k0 & (DIM - 1);
        #pragma unroll
        for (int ci = 0; ci < 4; ci++) {
            cp16(st + rowoff + ci * 16,                 ap   + d0 + ci * 8);
            cp16(st + MAT_BYTES + rowoff + ci * 16,     bhip + k0 + ci * 8);
            cp16(st + 2 * MAT_BYTES + rowoff + ci * 16, blop + k0 + ci * 8);
        }
        cp_commit();
    };

    // ---- compute role: 4(M) x 4(N) warp grid, 32x32 warp tile ----
    int wm = (wid >> 2) * 32;
    int wn = (wid & 3) * 32;
    int arow = lane & 15;
    int acol = (lane >> 4) * 8;
    int q    = lane >> 3, rl = lane & 7;
    int brow = wn + ((q >= 2) ? 8 : 0) + rl;
    int bcol = (q & 1) * 8;
    const uint32_t aOff = (uint32_t)((wm + arow) * PAD + acol) * 2;
    const uint32_t bOff = (uint32_t)MAT_BYTES + (uint32_t)(brow * PAD + bcol) * 2;
    int g = lane >> 2;

    float acc[2][4][4];
    float seg[2][4][4];
    #pragma unroll
    for (int i = 0; i < 2; i++)
        #pragma unroll
        for (int j = 0; j < 4; j++)
            #pragma unroll
            for (int e = 0; e < 4; e++) acc[i][j][e] = 0.f;

    // ---- prologue ----
    for (int idx = tid; idx < 128 * NEXP; idx += 512)
        swgt[idx] = wgt[(size_t)(bm + (idx >> 3)) * NEXP + (idx & 7)];
    load_chunk(0);

    int c = 0;
    for (int e = 0; e < NEXP; e++) {
        #pragma unroll
        for (int i = 0; i < 2; i++)
            #pragma unroll
            for (int j = 0; j < 4; j++)
                #pragma unroll
                for (int t = 0; t < 4; t++) seg[i][j][t] = 0.f;

        for (int dc = 0; dc < NCHUNK / NEXP; dc++, c++) {
            cp_wait<0>();          // chunk c copies retired (only group outstanding)
            __syncthreads();       // data visible; prev compute done -> buffer free
            if (c + 1 < NCHUNK) load_chunk(c + 1);   // overlaps compute(c)

            uint32_t st = sb + (uint32_t)(c & 1) * STAGE_BYTES;
            uint32_t aHi = st + aOff;
            uint32_t bHi = st + bOff;

            #pragma unroll
            for (int ks = 0; ks < BK / 16; ks++) {
                uint32_t kb = (uint32_t)(ks * 16) * 2;
                uint32_t bh[4][2], bl[4][2];
                #pragma unroll
                for (int p = 0; p < 2; p++) {
                    uint32_t ba = bHi + (uint32_t)(p * 16 * PAD) * 2 + kb;
                    LDSM4(bh[2*p][0], bh[2*p][1], bh[2*p+1][0], bh[2*p+1][1], ba);
                    LDSM4(bl[2*p][0], bl[2*p][1], bl[2*p+1][0], bl[2*p+1][1], ba + MAT_BYTES);
                }
                uint32_t ah[2][4];
                #pragma unroll
                for (int mt = 0; mt < 2; mt++) {
                    uint32_t aa = aHi + (uint32_t)(mt * 16 * PAD) * 2 + kb;
                    LDSM4(ah[mt][0], ah[mt][1], ah[mt][2], ah[mt][3], aa);
                }
                // pass-major: 8 independent accumulators between same-acc reuse
                #pragma unroll
                for (int mt = 0; mt < 2; mt++)
                    #pragma unroll
                    for (int nt = 0; nt < 4; nt++)
                        mma_f16(seg[mt][nt], ah[mt], bh[nt]);
                #pragma unroll
                for (int mt = 0; mt < 2; mt++)
                    #pragma unroll
                    for (int nt = 0; nt < 4; nt++)
                        mma_f16(seg[mt][nt], ah[mt], bl[nt]);
            }
            __syncthreads();       // compute(c) done before next overwrite of buffer
        }

        // ---- expert boundary: acc += w(row, e) * seg ----
        #pragma unroll
        for (int mt = 0; mt < 2; mt++) {
            float w0 = swgt[(wm + mt * 16 + g) * NEXP + e];
            float w1 = swgt[(wm + mt * 16 + 8 + g) * NEXP + e];
            #pragma unroll
            for (int nt = 0; nt < 4; nt++) {
                acc[mt][nt][0] += w0 * seg[mt][nt][0];
                acc[mt][nt][1] += w0 * seg[mt][nt][1];
                acc[mt][nt][2] += w1 * seg[mt][nt][2];
                acc[mt][nt][3] += w1 * seg[mt][nt][3];
            }
        }
    }

    // ---- epilogue ----
    int tig = lane & 3;
    #pragma unroll
    for (int mt = 0; mt < 2; mt++) {
        #pragma unroll
        for (int nt = 0; nt < 4; nt++) {
            int row = bm + wm + mt * 16 + g;
            int col = bn + wn + nt * 8 + tig * 2;
            *(float2*)(out + (size_t)row * DIM + col) =
                make_float2(acc[mt][nt][0], acc[mt][nt][1]);
            *(float2*)(out + (size_t)(row + 8) * DIM + col) =
                make_float2(acc[mt][nt][2], acc[mt][nt][3]);
        }
    }
}

// ---------------------------------------------------------------------------
// Router: 48 logits per token (8 in / 32 proc / 8 out), softmax8 x2 + top-3
// ---------------------------------------------------------------------------
__global__ void router_kernel(const float* __restrict__ act,
                              const float* __restrict__ Wi,
                              const float* __restrict__ Wp,
                              const float* __restrict__ Wo,
                              float* __restrict__ inw,
                              int*   __restrict__ pidx,
                              float* __restrict__ outw)
{
    int t    = blockIdx.x;
    int tid  = threadIdx.x;
    int lane = tid & 31, warp = tid >> 5;
    __shared__ float xs[DIM];
    __shared__ float lg[48];

    const float* xr = act + (size_t)t * DIM;
    for (int i = tid; i < DIM; i += 128) xs[i] = xr[i];
    __syncthreads();

    for (int l = warp; l < 48; l += 4) {
        const float* wr = (l < 8) ? (Wi + (size_t)l * DIM)
                        : (l < 40) ? (Wp + (size_t)(l - 8) * DIM)
                                   : (Wo + (size_t)(l - 40) * DIM);
        float s = 0.f;
        for (int d = lane; d < DIM; d += 32) s += xs[d] * wr[d];
        #pragma unroll
        for (int off = 16; off > 0; off >>= 1)
            s += __shfl_xor_sync(0xffffffffu, s, off);
        if (lane == 0) lg[l] = s;
    }
    __syncthreads();

    if (tid == 0) {
        float m = lg[0];
        for (int i = 1; i < 8; i++) m = fmaxf(m, lg[i]);
        float e[8], sum = 0.f;
        for (int i = 0; i < 8; i++) { e[i] = expf(lg[i] - m); sum += e[i]; }
        for (int i = 0; i < 8; i++) inw[t * 8 + i] = e[i] / sum;

        bool used[NPROC];
        for (int n = 0; n < NPROC; n++) used[n] = false;
        for (int r = 0; r < TOPK; r++) {
            float best = -INFINITY; int bi = 0;
            for (int n = 0; n < NPROC; n++)
                if (!used[n] && lg[8 + n] > best) { best = lg[8 + n]; bi = n; }
            used[bi] = true;
            pidx[t * TOPK + r] = bi;
        }

        m = lg[40];
        for (int i = 1; i < 8; i++) m = fmaxf(m, lg[40 + i]);
        sum = 0.f;
        for (int i = 0; i < 8; i++) { e[i] = expf(lg[40 + i] - m); sum += e[i]; }
        for (int i = 0; i < 8; i++) outw[t * 8 + i] = e[i] / sum;
    }
}

// ---------------------------------------------------------------------------
// Householder reflections (z-batched): h -= 2 (h.v)/(v.v + 1e-8) v, 3x/token;
// writes fp16 output to slot z.
// ---------------------------------------------------------------------------
__global__ void householder_kernel(const float* __restrict__ hbase,
                                   const float* __restrict__ v0,
                                   const float* __restrict__ v1,
                                   const float* __restrict__ v2,
                                   const int* __restrict__ pidx,
                                   __half* __restrict__ outB)
{
    int t = blockIdx.x, tid = threadIdx.x;
    int z = blockIdx.y;
    int lane = tid & 31, warp = tid >> 5;
    const float* vproc = (z == 0) ? v0 : (z == 1) ? v1 : v2;
    const float* hr = hbase + ((size_t)z * TOK + t) * DIM;
    __half* oh = outB + ((size_t)z * TOK + t) * DIM;

    float hv[4];
    #pragma unroll
    for (int i = 0; i < 4; i++) hv[i] = hr[tid + 256 * i];

    __shared__ float sred[16];

    for (int rfl = 0; rfl < TOPK; rfl++) {
        int idx = pidx[t * TOPK + rfl];
        const float* v = vproc + (size_t)idx * DIM;
        float vr[4];
        float d1 = 0.f, d2 = 0.f;
        #pragma unroll
        for (int i = 0; i < 4; i++) {
            vr[i] = v[tid + 256 * i];
            d1 += hv[i] * vr[i];
            d2 += vr[i] * vr[i];
        }
        #pragma unroll
        for (int off = 16; off > 0; off >>= 1) {
            d1 += __shfl_xor_sync(0xffffffffu, d1, off);
            d2 += __shfl_xor_sync(0xffffffffu, d2, off);
        }
        if (lane == 0) { sred[warp] = d1; sred[8 + warp] = d2; }
        __syncthreads();
        float t1 = 0.f, t2 = 0.f;
        #pragma unroll
        for (int w = 0; w < 8; w++) { t1 += sred[w]; t2 += sred[8 + w]; }
        float f = 2.f * t1 / (t2 + 1e-8f);
        #pragma unroll
        for (int i = 0; i < 4; i++) hv[i] -= f * vr[i];
        __syncthreads();
    }

    #pragma unroll
    for (int i = 0; i < 4; i++)
        oh[tid + 256 * i] = __float2half_rn(hv[i]);
}

// ---------------------------------------------------------------------------
// Causal attention, online softmax (fp32). 32 q-rows per block (512 thr),
// 2 rows per warp sharing K/V smem reads; float4 staging; lane-per-key
// within 32-key batches. Dynamic smem.
// ---------------------------------------------------------------------------
__global__ __launch_bounds__(512)
void attn_kernel(const float* __restrict__ Q,
                 const float* __restrict__ K,
                 const float* __restrict__ V,
                 float* __restrict__ O)
{
    extern __shared__ float asm_buf[];
    float* Ks = asm_buf + ATTN_KS_OFF;   // [32][KS_STRIDE]
    float* Vs = asm_buf + ATTN_VS_OFF;   // [32][KS_STRIDE]
    float* qs = asm_buf + ATTN_QS_OFF;   // [32][QS_STRIDE]

    const float scale = 0.08838834764831845f;  // 1/sqrt(128)
    int bh = blockIdx.y;
    int b = bh >> 3, hh = bh & 7;
    int q0 = blockIdx.x * 32;
    int tid = threadIdx.x, lane = tid & 31, warp = tid >> 5;

    const float* Qb = Q + (size_t)b * SEQ * DIM + hh * DHEAD;
    const float* Kb = K + (size_t)b * SEQ * DIM + hh * DHEAD;
    const float* Vb = V + (size_t)b * SEQ * DIM + hh * DHEAD;
    float*       Ob = O + (size_t)b * SEQ * DIM + hh * DHEAD;

    int row0 = q0 + warp;
    int row1 = q0 + 16 + warp;

    for (int idx = tid; idx < 32 * 32; idx += 512) {
        int j = idx >> 5, d4 = idx & 31;
        ((float4*)&qs[j * QS_STRIDE])[d4] =
            ((const float4*)(Qb + (size_t)(q0 + j) * DIM))[d4];
    }

    float acc0[4] = {0.f, 0.f, 0.f, 0.f};
    float acc1[4] = {0.f, 0.f, 0.f, 0.f};
    float mi0 = -1e30f, li0 = 0.f;
    float mi1 = -1e30f, li1 = 0.f;

    int kend = q0 + 32;
    for (int c0 = 0; c0 < kend; c0 += 32) {
        __syncthreads();
        for (int idx = tid; idx < 32 * 32; idx += 512) {
            int j = idx >> 5, d4 = idx & 31;
            ((float4*)&Ks[j * KS_STRIDE])[d4] =
                ((const float4*)(Kb + (size_t)(c0 + j) * DIM))[d4];
            ((float4*)&Vs[j * KS_STRIDE])[d4] =
                ((const float4*)(Vb + (size_t)(c0 + j) * DIM))[d4];
        }
        __syncthreads();

        int kg = c0 + lane;
        const float4* kr  = (const float4*)&Ks[lane * KS_STRIDE];
        const float4* qr0 = (const float4*)&qs[warp * QS_STRIDE];
        const float4* qr1 = (const float4*)&qs[(warp + 16) * QS_STRIDE];
        float s0 = 0.f, s1 = 0.f;
        #pragma unroll
        for (int w = 0; w < 32; w++) {
            float4 kk = kr[w];
            float4 qa = qr0[w];
            float4 qb = qr1[w];
            s0 += qa.x * kk.x + qa.y * kk.y + qa.z * kk.z + qa.w * kk.w;
            s1 += qb.x * kk.x + qb.y * kk.y + qb.z * kk.z + qb.w * kk.w;
        }
        s0 *= scale;
        s1 *= scale;
        if (kg > row0) s0 = -1e30f;
        if (kg > row1) s1 = -1e30f;

        float mb0 = s0, mb1 = s1;
        #pragma unroll
        for (int off = 16; off > 0; off >>= 1) {
            mb0 = fmaxf(mb0, __shfl_xor_sync(0xffffffffu, mb0, off));
            mb1 = fmaxf(mb1, __shfl_xor_sync(0xffffffffu, mb1, off));
        }
        float mn0 = fmaxf(mi0, mb0);
        float mn1 = fmaxf(mi1, mb1);
        float cr0 = expf(mi0 - mn0);
        float cr1 = expf(mi1 - mn1);
        float p0 = expf(s0 - mn0);
        float p1 = expf(s1 - mn1);
        float ps0 = p0, ps1 = p1;
        #pragma unroll
        for (int off = 16; off > 0; off >>= 1) {
            ps0 += __shfl_xor_sync(0xffffffffu, ps0, off);
            ps1 += __shfl_xor_sync(0xffffffffu, ps1, off);
        }
        li0 = li0 * cr0 + ps0;
        li1 = li1 * cr1 + ps1;

        #pragma unroll
        for (int i = 0; i < 4; i++) { acc0[i] *= cr0; acc1[i] *= cr1; }
        #pragma unroll
        for (int j = 0; j < 32; j++) {
            float pj0 = __shfl_sync(0xffffffffu, p0, j);
            float pj1 = __shfl_sync(0xffffffffu, p1, j);
            float4 vv = *(const float4*)&Vs[j * KS_STRIDE + lane * 4];
            acc0[0] += pj0 * vv.x;  acc0[1] += pj0 * vv.y;
            acc0[2] += pj0 * vv.z;  acc0[3] += pj0 * vv.w;
            acc1[0] += pj1 * vv.x;  acc1[1] += pj1 * vv.y;
            acc1[2] += pj1 * vv.z;  acc1[3] += pj1 * vv.w;
        }
        mi0 = mn0;
        mi1 = mn1;
    }

    float inv0 = 1.f / li0;
    float inv1 = 1.f / li1;
    *(float4*)(Ob + (size_t)row0 * DIM + lane * 4) =
        make_float4(acc0[0] * inv0, acc0[1] * inv0, acc0[2] * inv0, acc0[3] * inv0);
    *(float4*)(Ob + (size_t)row1 * DIM + lane * 4) =
        make_float4(acc1[0] * inv1, acc1[1] * inv1, acc1[2] * inv1, acc1[3] * inv1);
}

// ---------------------------------------------------------------------------
// Launch
// ---------------------------------------------------------------------------
extern "C" void kernel_launch(void* const* d_in, const int* in_sizes, int n_in,
                              void* d_out, int out_size)
{
    const float* x       = (const float*)d_in[0];
    const float* Wr_in   = (const float*)d_in[2];
    const float* Wr_proc = (const float*)d_in[3];
    const float* Wr_out  = (const float*)d_in[4];
    const float* WrO_in  = (const float*)d_in[5];
    const float* WrO_proc= (const float*)d_in[6];
    const float* WrO_out = (const float*)d_in[7];
    const float* Wq_in   = (const float*)d_in[8];
    const float* vq      = (const float*)d_in[9];
    const float* Wq_out  = (const float*)d_in[10];
    const float* Wk_in   = (const float*)d_in[11];
    const float* vk      = (const float*)d_in[12];
    const float* Wk_out  = (const float*)d_in[13];
    const float* Wv_in   = (const float*)d_in[14];
    const float* vv      = (const float*)d_in[15];
    const float* Wv_out  = (const float*)d_in[16];
    const float* Wo_in   = (const float*)d_in[17];
    const float* vo      = (const float*)d_in[18];
    const float* Wo_out  = (const float*)d_in[19];
    float* out = (float*)d_out;

    float *h, *Q, *Kc, *V, *O, *inw, *outw;
    int* pidx;
    __half *whi, *wlo, *xh, *hh;
    cudaGetSymbolAddress((void**)&h,    g_h);
    cudaGetSymbolAddress((void**)&Q,    g_Q);
    cudaGetSymbolAddress((void**)&Kc,   g_Kc);
    cudaGetSymbolAddress((void**)&V,    g_V);
    cudaGetSymbolAddress((void**)&O,    g_O);
    cudaGetSymbolAddress((void**)&inw,  g_inw);
    cudaGetSymbolAddress((void**)&outw, g_outw);
    cudaGetSymbolAddress((void**)&pidx, g_pidx);
    cudaGetSymbolAddress((void**)&whi,  g_whi);
    cudaGetSymbolAddress((void**)&wlo,  g_wlo);
    cudaGetSymbolAddress((void**)&xh,   g_xh);
    cudaGetSymbolAddress((void**)&hh,   g_hh);

    cudaFuncSetAttribute(circuit_gemm_tc,
                         cudaFuncAttributeMaxDynamicSharedMemorySize,
                         SMEM_GEMM_BYTES);
    cudaFuncSetAttribute(attn_kernel,
                         cudaFuncAttributeMaxDynamicSharedMemorySize,
                         SMEM_ATTN_BYTES);

    dim3 gGemm3(DIM / 128, TOK / 128, 3);   // 768 CTAs
    dim3 gGemm1(DIM / 128, TOK / 128, 1);   // 256 CTAs
    dim3 gPrep8(DIM / 32, KTOT / 32, 8);    // all 8 weight slots, upfront
    int  gSplit = TOK * DIM / (256 * 4);    // 4096

    // ---- All weight preps upfront (weights independent of activations) ----
    prep_w_kernel<<<gPrep8, 256>>>(Wq_in, Wk_in, Wv_in, Wq_out, Wk_out, Wv_out,
                                   Wo_in, Wo_out, whi, wlo);

    // ---- Router on x + x convert ----
    router_kernel<<<TOK, 128>>>(x, Wr_in, Wr_proc, Wr_out, inw, pidx, outw);
    split_kernel<<<gSplit, 256>>>(x, xh);

    // ---- Q/K/V in-projections (slots 0-2) ----
    circuit_gemm_tc<<<gGemm3, 512, SMEM_GEMM_BYTES>>>(
        xh, 0, whi, wlo, inw, h, h + ASZ, h + 2 * ASZ);

    // ---- Householders (fused) ----
    householder_kernel<<<dim3(TOK, 3), 256>>>(h, vq, vk, vv, pidx, hh);

    // ---- Q/K/V out-projections (slots 3-5) ----
    circuit_gemm_tc<<<gGemm3, 512, SMEM_GEMM_BYTES>>>(
        hh, ASZ, whi + 3 * WSZ, wlo + 3 * WSZ, outw, Q, Kc, V);

    // ---- Attention ----
    attn_kernel<<<dim3(SEQ / 32, NBATCH * NH), 512, SMEM_ATTN_BYTES>>>(Q, Kc, V, O);

    // ---- Router on O + output circuit (slots 6, 7) ----
    router_kernel<<<TOK, 128>>>(O, WrO_in, WrO_proc, WrO_out, inw, pidx, outw);
    split_kernel<<<gSplit, 256>>>(O, xh);
    circuit_gemm_tc<<<gGemm1, 512, SMEM_GEMM_BYTES>>>(
        xh, 0, whi + 6 * WSZ, wlo + 6 * WSZ, inw, h, h, h);
    householder_kernel<<<dim3(TOK, 1), 256>>>(h, vo, vo, vo, pidx, hh);
    circuit_gemm_tc<<<gGemm1, 512, SMEM_GEMM_BYTES>>>(
        hh, 0, whi + 7 * WSZ, wlo + 7 * WSZ, outw, out, out, out);

    (void)in_sizes; (void)n_in; (void)out_size;
}

// round 16
// speedup vs baseline: 1.1504x; 1.1504x over previous
#include <cuda_runtime.h>
#include <cuda_fp16.h>
#include <math.h>
#include <stdint.h>

// Problem constants
#define TOK   4096      // B*S
#define DIM   1024      // D == R
#define SEQ   2048
#define NBATCH 2
#define NH    8
#define DHEAD 128
#define NEXP  8
#define NPROC 32
#define TOPK  3
#define KTOT  8192      // NEXP * DIM
#define WSZ   ((size_t)DIM * KTOT)   // elements per weight slot
#define ASZ   ((size_t)TOK * DIM)

// GEMM tiling: 128x128xBK64, 512 threads, 3 stages, fp16 2-pass (R14 config)
#define BK      64
#define NCHUNK  (KTOT / BK)           // 128
#define PAD     72                    // smem row stride in fp16 halves (144B)
#define MAT_BYTES   (128 * PAD * 2)   // 18432 per matrix
#define STAGE_BYTES (3 * MAT_BYTES)   // A, Bhi, Blo
#define NSTAGE  3
#define SMEM_GEMM_BYTES (NSTAGE * STAGE_BYTES)   // 165888

// Attention smem layout (dynamic): Ks[32][132] | Vs[32][132] | qs[32][128]
#define KS_STRIDE 132
#define QS_STRIDE 128
#define ATTN_KS_OFF 0
#define ATTN_VS_OFF (32 * KS_STRIDE)
#define ATTN_QS_OFF (2 * 32 * KS_STRIDE)
#define SMEM_ATTN_BYTES ((2 * 32 * KS_STRIDE + 32 * QS_STRIDE) * 4)   // 50176

// Weight slots: 0=Wq_in 1=Wk_in 2=Wv_in 3=Wq_out 4=Wk_out 5=Wv_out 6=Wo_in 7=Wo_out
// ---------------------------------------------------------------------------
// Scratch (device globals — no runtime allocation allowed)
// ---------------------------------------------------------------------------
__device__ float g_h  [3 * TOK * DIM];
__device__ float g_Q  [TOK * DIM];
__device__ float g_Kc [TOK * DIM];
__device__ float g_V  [TOK * DIM];
__device__ float g_O  [TOK * DIM];
__device__ float g_inw [TOK * NEXP];
__device__ float g_outw[TOK * NEXP];
__device__ int   g_pidx[TOK * TOPK];
__device__ __half g_whi[8 * DIM * KTOT];   // weightT hi, 8 slots [N=1024, K=8192]
__device__ __half g_wlo[8 * DIM * KTOT];
__device__ __half g_xh [TOK * DIM];        // activation fp16 (x / O)
__device__ __half g_hh [3 * TOK * DIM];    // householder output fp16

// ---------------------------------------------------------------------------
// Portable tensor-core helpers (sm_80+ PTX; no 'a'-suffix features)
// ---------------------------------------------------------------------------
#define LDSM4(r0, r1, r2, r3, addr) \
    asm volatile("ldmatrix.sync.aligned.m8n8.x4.shared.b16 {%0,%1,%2,%3}, [%4];" \
                 : "=r"(r0), "=r"(r1), "=r"(r2), "=r"(r3) : "r"(addr))

__device__ __forceinline__ void mma_f16(float* c, const uint32_t* a, const uint32_t* b) {
    asm volatile(
        "mma.sync.aligned.m16n8k16.row.col.f32.f16.f16.f32 "
        "{%0,%1,%2,%3}, {%4,%5,%6,%7}, {%8,%9}, {%0,%1,%2,%3};"
        : "+f"(c[0]), "+f"(c[1]), "+f"(c[2]), "+f"(c[3])
        : "r"(a[0]), "r"(a[1]), "r"(a[2]), "r"(a[3]), "r"(b[0]), "r"(b[1]));
}

__device__ __forceinline__ void cp16(uint32_t saddr, const void* gaddr) {
    asm volatile("cp.async.cg.shared.global [%0], [%1], 16;" :: "r"(saddr), "l"(gaddr));
}
__device__ __forceinline__ void cp_commit() {
    asm volatile("cp.async.commit_group;" ::: "memory");
}
template <int N>
__device__ __forceinline__ void cp_wait() {
    asm volatile("cp.async.wait_group %0;" :: "n"(N) : "memory");
}

__device__ __forceinline__ void split_f16(float v, __half& hi, __half& lo) {
    hi = __float2half_rn(v);
    lo = __float2half_rn(v - __half2float(hi));
}

// ---------------------------------------------------------------------------
// Weight prep (8-slot batched): W_z[KTOT, DIM] fp32 -> fp16 hi/lo [DIM, KTOT]
// ---------------------------------------------------------------------------
__global__ void prep_w_kernel(const float* __restrict__ W0,
                              const float* __restrict__ W1,
                              const float* __restrict__ W2,
                              const float* __restrict__ W3,
                              const float* __restrict__ W4,
                              const float* __restrict__ W5,
                              const float* __restrict__ W6,
                              const float* __restrict__ W7,
                              __half* __restrict__ Whi,
                              __half* __restrict__ Wlo)
{
    int z = blockIdx.z;
    const float* W = (z == 0) ? W0 : (z == 1) ? W1 : (z == 2) ? W2 : (z == 3) ? W3
                   : (z == 4) ? W4 : (z == 5) ? W5 : (z == 6) ? W6 : W7;
    __half* whi = Whi + (size_t)z * WSZ;
    __half* wlo = Wlo + (size_t)z * WSZ;

    __shared__ float ts[32][33];
    int k0 = blockIdx.y * 32, n0 = blockIdx.x * 32;
    int tx = threadIdx.x & 31, ty = threadIdx.x >> 5;   // 32 x 8
    #pragma unroll
    for (int r = 0; r < 4; r++) {
        int k = ty + r * 8;
        ts[k][tx] = W[(size_t)(k0 + k) * DIM + n0 + tx];
    }
    __syncthreads();
    #pragma unroll
    for (int r = 0; r < 4; r++) {
        int n = ty + r * 8;
        float v = ts[tx][n];                      // W[k0+tx][n0+n]
        __half h, l;
        split_f16(v, h, l);
        size_t o = (size_t)(n0 + n) * KTOT + k0 + tx;
        whi[o] = h;
        wlo[o] = l;
    }
}

// ---------------------------------------------------------------------------
// Activation convert: fp32 [TOK,DIM] -> fp16
// ---------------------------------------------------------------------------
__global__ void split_kernel(const float* __restrict__ src,
                             __half* __restrict__ dst)
{
    int i = (blockIdx.x * 256 + threadIdx.x) * 4;
    float4 v = *(const float4*)(src + i);
    __half h[4];
    h[0] = __float2half_rn(v.x);
    h[1] = __float2half_rn(v.y);
    h[2] = __float2half_rn(v.z);
    h[3] = __float2half_rn(v.w);
    *(uint64_t*)(dst + i) = *(uint64_t*)h;
}

// ---------------------------------------------------------------------------
// Tensor-core mixture GEMM via mma.sync (fp16 A + hi/lo B, 2 passes, fp32 acc).
// z-batched: blockIdx.z selects A (via aStride), weight slot, and output.
// 512 threads / 16 warps: 4(M) x 4(N) warp grid, 32x32 warp tile, 3 stages.
// ---------------------------------------------------------------------------
__global__ __launch_bounds__(512)
void circuit_gemm_tc(const __half* __restrict__ A,      // base, + z*aStride
                     size_t aStride,
                     const __half* __restrict__ WhiB,   // slot base (z-indexed)
                     const __half* __restrict__ WloB,
                     const float* __restrict__ wgt,     // [TOK, NEXP]
                     float* __restrict__ o0,
                     float* __restrict__ o1,
                     float* __restrict__ o2)
{
    extern __shared__ char smem[];
    __shared__ float swgt[128 * NEXP];
    const uint32_t sb = (uint32_t)__cvta_generic_to_shared(smem);
    int tid = threadIdx.x, lane = tid & 31, wid = tid >> 5;
    int bm = blockIdx.y * 128, bn = blockIdx.x * 128;
    int z  = blockIdx.z;
    const __half* AZ  = A + (size_t)z * aStride;
    const __half* Whi = WhiB + (size_t)z * WSZ;
    const __half* Wlo = WloB + (size_t)z * WSZ;
    float* out = (z == 0) ? o0 : (z == 1) ? o1 : o2;

    // ---- loader role: 4 threads per row, 16-k quarter each ----
    int r  = tid >> 2;                 // 0..127
    int kq = (tid & 3) * 16;           // k quarter
    const __half* ap   = AZ  + (size_t)(bm + r) * DIM + kq;
    const __half* bhip = Whi + (size_t)(bn + r) * KTOT + kq;
    const __half* blop = Wlo + (size_t)(bn + r) * KTOT + kq;
    const uint32_t rowoff = (uint32_t)(r * PAD + kq) * 2;

    auto load_chunk = [&](int c) {
        uint32_t st = sb + (uint32_t)(c % NSTAGE) * STAGE_BYTES;
        int k0 = c * BK;
        int d0 = k0 & (DIM - 1);
        #pragma unroll
        for (int ci = 0; ci < 2; ci++) {
            cp16(st + rowoff + ci * 16,                 ap   + d0 + ci * 8);
            cp16(st + MAT_BYTES + rowoff + ci * 16,     bhip + k0 + ci * 8);
            cp16(st + 2 * MAT_BYTES + rowoff + ci * 16, blop + k0 + ci * 8);
        }
        cp_commit();
    };

    // ---- compute role: 4(M) x 4(N) warp grid, 32x32 warp tile ----
    int wm = (wid >> 2) * 32;
    int wn = (wid & 3) * 32;
    int arow = lane & 15;
    int acol = (lane >> 4) * 8;
    int q    = lane >> 3, rl = lane & 7;
    int brow = wn + ((q >= 2) ? 8 : 0) + rl;
    int bcol = (q & 1) * 8;
    const uint32_t aOff = (uint32_t)((wm + arow) * PAD + acol) * 2;
    const uint32_t bOff = (uint32_t)MAT_BYTES + (uint32_t)(brow * PAD + bcol) * 2;
    int g = lane >> 2;

    float acc[2][4][4];
    float seg[2][4][4];
    #pragma unroll
    for (int i = 0; i < 2; i++)
        #pragma unroll
        for (int j = 0; j < 4; j++)
            #pragma unroll
            for (int e = 0; e < 4; e++) acc[i][j][e] = 0.f;

    // ---- prologue ----
    for (int idx = tid; idx < 128 * NEXP; idx += 512)
        swgt[idx] = wgt[(size_t)(bm + (idx >> 3)) * NEXP + (idx & 7)];
    load_chunk(0);
    load_chunk(1);

    int c = 0;
    for (int e = 0; e < NEXP; e++) {
        #pragma unroll
        for (int i = 0; i < 2; i++)
            #pragma unroll
            for (int j = 0; j < 4; j++)
                #pragma unroll
                for (int t = 0; t < 4; t++) seg[i][j][t] = 0.f;

        for (int dc = 0; dc < 16; dc++, c++) {
            if (c + 1 < NCHUNK) cp_wait<1>(); else cp_wait<0>();
            __syncthreads();
            if (c + 2 < NCHUNK) load_chunk(c + 2);

            uint32_t st = sb + (uint32_t)(c % NSTAGE) * STAGE_BYTES;
            uint32_t aHi = st + aOff;
            uint32_t bHi = st + bOff;

            #pragma unroll
            for (int ks = 0; ks < 4; ks++) {
                uint32_t kb = (uint32_t)(ks * 16) * 2;
                uint32_t bh[4][2], bl[4][2];
                #pragma unroll
                for (int p = 0; p < 2; p++) {
                    uint32_t ba = bHi + (uint32_t)(p * 16 * PAD) * 2 + kb;
                    LDSM4(bh[2*p][0], bh[2*p][1], bh[2*p+1][0], bh[2*p+1][1], ba);
                    LDSM4(bl[2*p][0], bl[2*p][1], bl[2*p+1][0], bl[2*p+1][1], ba + MAT_BYTES);
                }
                uint32_t ah[2][4];
                #pragma unroll
                for (int mt = 0; mt < 2; mt++) {
                    uint32_t aa = aHi + (uint32_t)(mt * 16 * PAD) * 2 + kb;
                    LDSM4(ah[mt][0], ah[mt][1], ah[mt][2], ah[mt][3], aa);
                }
                // pass-major: 8 independent accumulators between same-acc reuse
                #pragma unroll
                for (int mt = 0; mt < 2; mt++)
                    #pragma unroll
                    for (int nt = 0; nt < 4; nt++)
                        mma_f16(seg[mt][nt], ah[mt], bh[nt]);
                #pragma unroll
                for (int mt = 0; mt < 2; mt++)
                    #pragma unroll
                    for (int nt = 0; nt < 4; nt++)
                        mma_f16(seg[mt][nt], ah[mt], bl[nt]);
            }
        }

        // ---- expert boundary: acc += w(row, e) * seg ----
        #pragma unroll
        for (int mt = 0; mt < 2; mt++) {
            float w0 = swgt[(wm + mt * 16 + g) * NEXP + e];
            float w1 = swgt[(wm + mt * 16 + 8 + g) * NEXP + e];
            #pragma unroll
            for (int nt = 0; nt < 4; nt++) {
                acc[mt][nt][0] += w0 * seg[mt][nt][0];
                acc[mt][nt][1] += w0 * seg[mt][nt][1];
                acc[mt][nt][2] += w1 * seg[mt][nt][2];
                acc[mt][nt][3] += w1 * seg[mt][nt][3];
            }
        }
    }

    // ---- epilogue ----
    int tig = lane & 3;
    #pragma unroll
    for (int mt = 0; mt < 2; mt++) {
        #pragma unroll
        for (int nt = 0; nt < 4; nt++) {
            int row = bm + wm + mt * 16 + g;
            int col = bn + wn + nt * 8 + tig * 2;
            *(float2*)(out + (size_t)row * DIM + col) =
                make_float2(acc[mt][nt][0], acc[mt][nt][1]);
            *(float2*)(out + (size_t)(row + 8) * DIM + col) =
                make_float2(acc[mt][nt][2], acc[mt][nt][3]);
        }
    }
}

// ---------------------------------------------------------------------------
// Router: 48 logits per token (8 in / 32 proc / 8 out), softmax8 x2 + top-3
// ---------------------------------------------------------------------------
__global__ void router_kernel(const float* __restrict__ act,
                              const float* __restrict__ Wi,
                              const float* __restrict__ Wp,
                              const float* __restrict__ Wo,
                              float* __restrict__ inw,
                              int*   __restrict__ pidx,
                              float* __restrict__ outw)
{
    int t    = blockIdx.x;
    int tid  = threadIdx.x;
    int lane = tid & 31, warp = tid >> 5;
    __shared__ float xs[DIM];
    __shared__ float lg[48];

    const float* xr = act + (size_t)t * DIM;
    for (int i = tid; i < DIM; i += 128) xs[i] = xr[i];
    __syncthreads();

    for (int l = warp; l < 48; l += 4) {
        const float* wr = (l < 8) ? (Wi + (size_t)l * DIM)
                        : (l < 40) ? (Wp + (size_t)(l - 8) * DIM)
                                   : (Wo + (size_t)(l - 40) * DIM);
        float s = 0.f;
        for (int d = lane; d < DIM; d += 32) s += xs[d] * wr[d];
        #pragma unroll
        for (int off = 16; off > 0; off >>= 1)
            s += __shfl_xor_sync(0xffffffffu, s, off);
        if (lane == 0) lg[l] = s;
    }
    __syncthreads();

    if (tid == 0) {
        float m = lg[0];
        for (int i = 1; i < 8; i++) m = fmaxf(m, lg[i]);
        float e[8], sum = 0.f;
        for (int i = 0; i < 8; i++) { e[i] = expf(lg[i] - m); sum += e[i]; }
        for (int i = 0; i < 8; i++) inw[t * 8 + i] = e[i] / sum;

        bool used[NPROC];
        for (int n = 0; n < NPROC; n++) used[n] = false;
        for (int r = 0; r < TOPK; r++) {
            float best = -INFINITY; int bi = 0;
            for (int n = 0; n < NPROC; n++)
                if (!used[n] && lg[8 + n] > best) { best = lg[8 + n]; bi = n; }
            used[bi] = true;
            pidx[t * TOPK + r] = bi;
        }

        m = lg[40];
        for (int i = 1; i < 8; i++) m = fmaxf(m, lg[40 + i]);
        sum = 0.f;
        for (int i = 0; i < 8; i++) { e[i] = expf(lg[40 + i] - m); sum += e[i]; }
        for (int i = 0; i < 8; i++) outw[t * 8 + i] = e[i] / sum;
    }
}

// ---------------------------------------------------------------------------
// Householder reflections (z-batched): h -= 2 (h.v)/(v.v + 1e-8) v, 3x/token;
// writes fp16 output to slot z.
// ---------------------------------------------------------------------------
__global__ void householder_kernel(const float* __restrict__ hbase,
                                   const float* __restrict__ v0,
                                   const float* __restrict__ v1,
                                   const float* __restrict__ v2,
                                   const int* __restrict__ pidx,
                                   __half* __restrict__ outB)
{
    int t = blockIdx.x, tid = threadIdx.x;
    int z = blockIdx.y;
    int lane = tid & 31, warp = tid >> 5;
    const float* vproc = (z == 0) ? v0 : (z == 1) ? v1 : v2;
    const float* hr = hbase + ((size_t)z * TOK + t) * DIM;
    __half* oh = outB + ((size_t)z * TOK + t) * DIM;

    float hv[4];
    #pragma unroll
    for (int i = 0; i < 4; i++) hv[i] = hr[tid + 256 * i];

    __shared__ float sred[16];

    for (int rfl = 0; rfl < TOPK; rfl++) {
        int idx = pidx[t * TOPK + rfl];
        const float* v = vproc + (size_t)idx * DIM;
        float vr[4];
        float d1 = 0.f, d2 = 0.f;
        #pragma unroll
        for (int i = 0; i < 4; i++) {
            vr[i] = v[tid + 256 * i];
            d1 += hv[i] * vr[i];
            d2 += vr[i] * vr[i];
        }
        #pragma unroll
        for (int off = 16; off > 0; off >>= 1) {
            d1 += __shfl_xor_sync(0xffffffffu, d1, off);
            d2 += __shfl_xor_sync(0xffffffffu, d2, off);
        }
        if (lane == 0) { sred[warp] = d1; sred[8 + warp] = d2; }
        __syncthreads();
        float t1 = 0.f, t2 = 0.f;
        #pragma unroll
        for (int w = 0; w < 8; w++) { t1 += sred[w]; t2 += sred[8 + w]; }
        float f = 2.f * t1 / (t2 + 1e-8f);
        #pragma unroll
        for (int i = 0; i < 4; i++) hv[i] -= f * vr[i];
        __syncthreads();
    }

    #pragma unroll
    for (int i = 0; i < 4; i++)
        oh[tid + 256 * i] = __float2half_rn(hv[i]);
}

// ---------------------------------------------------------------------------
// Causal attention, online softmax (fp32). 32 q-rows per block (512 thr),
// 2 rows per warp sharing K/V smem reads; float4 staging; lane-per-key
// within 32-key batches. Dynamic smem.
// ---------------------------------------------------------------------------
__global__ __launch_bounds__(512)
void attn_kernel(const float* __restrict__ Q,
                 const float* __restrict__ K,
                 const float* __restrict__ V,
                 float* __restrict__ O)
{
    extern __shared__ float asm_buf[];
    float* Ks = asm_buf + ATTN_KS_OFF;   // [32][KS_STRIDE]
    float* Vs = asm_buf + ATTN_VS_OFF;   // [32][KS_STRIDE]
    float* qs = asm_buf + ATTN_QS_OFF;   // [32][QS_STRIDE]

    const float scale = 0.08838834764831845f;  // 1/sqrt(128)
    int bh = blockIdx.y;
    int b = bh >> 3, hh = bh & 7;
    int q0 = blockIdx.x * 32;
    int tid = threadIdx.x, lane = tid & 31, warp = tid >> 5;

    const float* Qb = Q + (size_t)b * SEQ * DIM + hh * DHEAD;
    const float* Kb = K + (size_t)b * SEQ * DIM + hh * DHEAD;
    const float* Vb = V + (size_t)b * SEQ * DIM + hh * DHEAD;
    float*       Ob = O + (size_t)b * SEQ * DIM + hh * DHEAD;

    int row0 = q0 + warp;
    int row1 = q0 + 16 + warp;

    for (int idx = tid; idx < 32 * 32; idx += 512) {
        int j = idx >> 5, d4 = idx & 31;
        ((float4*)&qs[j * QS_STRIDE])[d4] =
            ((const float4*)(Qb + (size_t)(q0 + j) * DIM))[d4];
    }

    float acc0[4] = {0.f, 0.f, 0.f, 0.f};
    float acc1[4] = {0.f, 0.f, 0.f, 0.f};
    float mi0 = -1e30f, li0 = 0.f;
    float mi1 = -1e30f, li1 = 0.f;

    int kend = q0 + 32;
    for (int c0 = 0; c0 < kend; c0 += 32) {
        __syncthreads();
        for (int idx = tid; idx < 32 * 32; idx += 512) {
            int j = idx >> 5, d4 = idx & 31;
            ((float4*)&Ks[j * KS_STRIDE])[d4] =
                ((const float4*)(Kb + (size_t)(c0 + j) * DIM))[d4];
            ((float4*)&Vs[j * KS_STRIDE])[d4] =
                ((const float4*)(Vb + (size_t)(c0 + j) * DIM))[d4];
        }
        __syncthreads();

        int kg = c0 + lane;
        const float4* kr  = (const float4*)&Ks[lane * KS_STRIDE];
        const float4* qr0 = (const float4*)&qs[warp * QS_STRIDE];
        const float4* qr1 = (const float4*)&qs[(warp + 16) * QS_STRIDE];
        float s0 = 0.f, s1 = 0.f;
        #pragma unroll
        for (int w = 0; w < 32; w++) {
            float4 kk = kr[w];
            float4 qa = qr0[w];
            float4 qb = qr1[w];
            s0 += qa.x * kk.x + qa.y * kk.y + qa.z * kk.z + qa.w * kk.w;
            s1 += qb.x * kk.x + qb.y * kk.y + qb.z * kk.z + qb.w * kk.w;
        }
        s0 *= scale;
        s1 *= scale;
        if (kg > row0) s0 = -1e30f;
        if (kg > row1) s1 = -1e30f;

        float mb0 = s0, mb1 = s1;
        #pragma unroll
        for (int off = 16; off > 0; off >>= 1) {
            mb0 = fmaxf(mb0, __shfl_xor_sync(0xffffffffu, mb0, off));
            mb1 = fmaxf(mb1, __shfl_xor_sync(0xffffffffu, mb1, off));
        }
        float mn0 = fmaxf(mi0, mb0);
        float mn1 = fmaxf(mi1, mb1);
        float cr0 = expf(mi0 - mn0);
        float cr1 = expf(mi1 - mn1);
        float p0 = expf(s0 - mn0);
        float p1 = expf(s1 - mn1);
        float ps0 = p0, ps1 = p1;
        #pragma unroll
        for (int off = 16; off > 0; off >>= 1) {
            ps0 += __shfl_xor_sync(0xffffffffu, ps0, off);
            ps1 += __shfl_xor_sync(0xffffffffu, ps1, off);
        }
        li0 = li0 * cr0 + ps0;
        li1 = li1 * cr1 + ps1;

        #pragma unroll
        for (int i = 0; i < 4; i++) { acc0[i] *= cr0; acc1[i] *= cr1; }
        #pragma unroll
        for (int j = 0; j < 32; j++) {
            float pj0 = __shfl_sync(0xffffffffu, p0, j);
            float pj1 = __shfl_sync(0xffffffffu, p1, j);
            float4 vv = *(const float4*)&Vs[j * KS_STRIDE + lane * 4];
            acc0[0] += pj0 * vv.x;  acc0[1] += pj0 * vv.y;
            acc0[2] += pj0 * vv.z;  acc0[3] += pj0 * vv.w;
            acc1[0] += pj1 * vv.x;  acc1[1] += pj1 * vv.y;
            acc1[2] += pj1 * vv.z;  acc1[3] += pj1 * vv.w;
        }
        mi0 = mn0;
        mi1 = mn1;
    }

    float inv0 = 1.f / li0;
    float inv1 = 1.f / li1;
    *(float4*)(Ob + (size_t)row0 * DIM + lane * 4) =
        make_float4(acc0[0] * inv0, acc0[1] * inv0, acc0[2] * inv0, acc0[3] * inv0);
    *(float4*)(Ob + (size_t)row1 * DIM + lane * 4) =
        make_float4(acc1[0] * inv1, acc1[1] * inv1, acc1[2] * inv1, acc1[3] * inv1);
}

// ---------------------------------------------------------------------------
// Launch
// ---------------------------------------------------------------------------
extern "C" void kernel_launch(void* const* d_in, const int* in_sizes, int n_in,
                              void* d_out, int out_size)
{
    const float* x       = (const float*)d_in[0];
    const float* Wr_in   = (const float*)d_in[2];
    const float* Wr_proc = (const float*)d_in[3];
    const float* Wr_out  = (const float*)d_in[4];
    const float* WrO_in  = (const float*)d_in[5];
    const float* WrO_proc= (const float*)d_in[6];
    const float* WrO_out = (const float*)d_in[7];
    const float* Wq_in   = (const float*)d_in[8];
    const float* vq      = (const float*)d_in[9];
    const float* Wq_out  = (const float*)d_in[10];
    const float* Wk_in   = (const float*)d_in[11];
    const float* vk      = (const float*)d_in[12];
    const float* Wk_out  = (const float*)d_in[13];
    const float* Wv_in   = (const float*)d_in[14];
    const float* vv      = (const float*)d_in[15];
    const float* Wv_out  = (const float*)d_in[16];
    const float* Wo_in   = (const float*)d_in[17];
    const float* vo      = (const float*)d_in[18];
    const float* Wo_out  = (const float*)d_in[19];
    float* out = (float*)d_out;

    float *h, *Q, *Kc, *V, *O, *inw, *outw;
    int* pidx;
    __half *whi, *wlo, *xh, *hh;
    cudaGetSymbolAddress((void**)&h,    g_h);
    cudaGetSymbolAddress((void**)&Q,    g_Q);
    cudaGetSymbolAddress((void**)&Kc,   g_Kc);
    cudaGetSymbolAddress((void**)&V,    g_V);
    cudaGetSymbolAddress((void**)&O,    g_O);
    cudaGetSymbolAddress((void**)&inw,  g_inw);
    cudaGetSymbolAddress((void**)&outw, g_outw);
    cudaGetSymbolAddress((void**)&pidx, g_pidx);
    cudaGetSymbolAddress((void**)&whi,  g_whi);
    cudaGetSymbolAddress((void**)&wlo,  g_wlo);
    cudaGetSymbolAddress((void**)&xh,   g_xh);
    cudaGetSymbolAddress((void**)&hh,   g_hh);

    cudaFuncSetAttribute(circuit_gemm_tc,
                         cudaFuncAttributeMaxDynamicSharedMemorySize,
                         SMEM_GEMM_BYTES);
    cudaFuncSetAttribute(attn_kernel,
                         cudaFuncAttributeMaxDynamicSharedMemorySize,
                         SMEM_ATTN_BYTES);

    dim3 gGemm3(DIM / 128, TOK / 128, 3);   // 768 CTAs
    dim3 gGemm1(DIM / 128, TOK / 128, 1);   // 256 CTAs
    dim3 gPrep8(DIM / 32, KTOT / 32, 8);    // all 8 weight slots, upfront
    int  gSplit = TOK * DIM / (256 * 4);    // 4096

    // ---- All weight preps upfront (weights independent of activations) ----
    prep_w_kernel<<<gPrep8, 256>>>(Wq_in, Wk_in, Wv_in, Wq_out, Wk_out, Wv_out,
                                   Wo_in, Wo_out, whi, wlo);

    // ---- Router on x + x convert ----
    router_kernel<<<TOK, 128>>>(x, Wr_in, Wr_proc, Wr_out, inw, pidx, outw);
    split_kernel<<<gSplit, 256>>>(x, xh);

    // ---- Q/K/V in-projections (slots 0-2) ----
    circuit_gemm_tc<<<gGemm3, 512, SMEM_GEMM_BYTES>>>(
        xh, 0, whi, wlo, inw, h, h + ASZ, h + 2 * ASZ);

    // ---- Householders (fused) ----
    householder_kernel<<<dim3(TOK, 3), 256>>>(h, vq, vk, vv, pidx, hh);

    // ---- Q/K/V out-projections (slots 3-5) ----
    circuit_gemm_tc<<<gGemm3, 512, SMEM_GEMM_BYTES>>>(
        hh, ASZ, whi + 3 * WSZ, wlo + 3 * WSZ, outw, Q, Kc, V);

    // ---- Attention ----
    attn_kernel<<<dim3(SEQ / 32, NBATCH * NH), 512, SMEM_ATTN_BYTES>>>(Q, Kc, V, O);

    // ---- Router on O + output circuit (slots 6, 7) ----
    router_kernel<<<TOK, 128>>>(O, WrO_in, WrO_proc, WrO_out, inw, pidx, outw);
    split_kernel<<<gSplit, 256>>>(O, xh);
    circuit_gemm_tc<<<gGemm1, 512, SMEM_GEMM_BYTES>>>(
        xh, 0, whi + 6 * WSZ, wlo + 6 * WSZ, inw, h, h, h);
    householder_kernel<<<dim3(TOK, 1), 256>>>(h, vo, vo, vo, pidx, hh);
    circuit_gemm_tc<<<gGemm1, 512, SMEM_GEMM_BYTES>>>(
        hh, 0, whi + 7 * WSZ, wlo + 7 * WSZ, outw, out, out, out);

    (void)in_sizes; (void)n_in; (void)out_size;
}

// round 17
// speedup vs baseline: 1.1539x; 1.0030x over previous
#include <cuda_runtime.h>
#include <cuda_fp16.h>
#include <math.h>
#include <stdint.h>

// Problem constants
#define TOK   4096      // B*S
#define DIM   1024      // D == R
#define SEQ   2048
#define NBATCH 2
#define NH    8
#define DHEAD 128
#define NEXP  8
#define NPROC 32
#define TOPK  3
#define KTOT  8192      // NEXP * DIM
#define WSZ   ((size_t)DIM * KTOT)   // elements per weight slot
#define ASZ   ((size_t)TOK * DIM)

// GEMM tiling: 128x128xBK64, 512 threads, 3 stages, fp16 2-pass
#define BK      64
#define NCHUNK  (KTOT / BK)           // 128
#define PAD     72                    // smem row stride in fp16 halves (144B)
#define MAT_BYTES   (128 * PAD * 2)   // 18432 per matrix
#define STAGE_BYTES (3 * MAT_BYTES)   // A, Bhi, Blo
#define NSTAGE  3
#define SMEM_GEMM_BYTES (NSTAGE * STAGE_BYTES)   // 165888

// Attention smem layout (dynamic): Ks[32][132] | Vs[32][132] | qs[32][128]
#define KS_STRIDE 132
#define QS_STRIDE 128
#define ATTN_KS_OFF 0
#define ATTN_VS_OFF (32 * KS_STRIDE)
#define ATTN_QS_OFF (2 * 32 * KS_STRIDE)
#define SMEM_ATTN_BYTES ((2 * 32 * KS_STRIDE + 32 * QS_STRIDE) * 4)   // 50176

// Weight slots: 0=Wq_in 1=Wk_in 2=Wv_in 3=Wq_out 4=Wk_out 5=Wv_out 6=Wo_in 7=Wo_out
// ---------------------------------------------------------------------------
// Scratch (device globals — no runtime allocation allowed)
// ---------------------------------------------------------------------------
__device__ float g_h  [3 * TOK * DIM];
__device__ float g_Q  [TOK * DIM];
__device__ float g_Kc [TOK * DIM];
__device__ float g_V  [TOK * DIM];
__device__ float g_O  [TOK * DIM];
__device__ float g_inw [TOK * NEXP];
__device__ float g_outw[TOK * NEXP];
__device__ int   g_pidx[TOK * TOPK];
__device__ __half g_whi[8 * DIM * KTOT];   // weightT hi, 8 slots [N=1024, K=8192]
__device__ __half g_wlo[8 * DIM * KTOT];
__device__ __half g_xh [TOK * DIM];        // activation fp16 (x / O)
__device__ __half g_hh [3 * TOK * DIM];    // householder output fp16

// ---------------------------------------------------------------------------
// Portable tensor-core helpers (sm_80+ PTX; no 'a'-suffix features)
// ---------------------------------------------------------------------------
#define LDSM4(r0, r1, r2, r3, addr) \
    asm volatile("ldmatrix.sync.aligned.m8n8.x4.shared.b16 {%0,%1,%2,%3}, [%4];" \
                 : "=r"(r0), "=r"(r1), "=r"(r2), "=r"(r3) : "r"(addr))

__device__ __forceinline__ void mma_f16(float* c, const uint32_t* a, const uint32_t* b) {
    asm volatile(
        "mma.sync.aligned.m16n8k16.row.col.f32.f16.f16.f32 "
        "{%0,%1,%2,%3}, {%4,%5,%6,%7}, {%8,%9}, {%0,%1,%2,%3};"
        : "+f"(c[0]), "+f"(c[1]), "+f"(c[2]), "+f"(c[3])
        : "r"(a[0]), "r"(a[1]), "r"(a[2]), "r"(a[3]), "r"(b[0]), "r"(b[1]));
}

__device__ __forceinline__ void cp16(uint32_t saddr, const void* gaddr) {
    asm volatile("cp.async.cg.shared.global [%0], [%1], 16;" :: "r"(saddr), "l"(gaddr));
}
__device__ __forceinline__ void cp_commit() {
    asm volatile("cp.async.commit_group;" ::: "memory");
}
template <int N>
__device__ __forceinline__ void cp_wait() {
    asm volatile("cp.async.wait_group %0;" :: "n"(N) : "memory");
}

__device__ __forceinline__ void split_f16(float v, __half& hi, __half& lo) {
    hi = __float2half_rn(v);
    lo = __float2half_rn(v - __half2float(hi));
}

// ---------------------------------------------------------------------------
// Weight prep (8-slot batched): W_z[KTOT, DIM] fp32 -> fp16 hi/lo [DIM, KTOT]
// ---------------------------------------------------------------------------
__global__ void prep_w_kernel(const float* __restrict__ W0,
                              const float* __restrict__ W1,
                              const float* __restrict__ W2,
                              const float* __restrict__ W3,
                              const float* __restrict__ W4,
                              const float* __restrict__ W5,
                              const float* __restrict__ W6,
                              const float* __restrict__ W7,
                              __half* __restrict__ Whi,
                              __half* __restrict__ Wlo)
{
    int z = blockIdx.z;
    const float* W = (z == 0) ? W0 : (z == 1) ? W1 : (z == 2) ? W2 : (z == 3) ? W3
                   : (z == 4) ? W4 : (z == 5) ? W5 : (z == 6) ? W6 : W7;
    __half* whi = Whi + (size_t)z * WSZ;
    __half* wlo = Wlo + (size_t)z * WSZ;

    __shared__ float ts[32][33];
    int k0 = blockIdx.y * 32, n0 = blockIdx.x * 32;
    int tx = threadIdx.x & 31, ty = threadIdx.x >> 5;   // 32 x 8
    #pragma unroll
    for (int r = 0; r < 4; r++) {
        int k = ty + r * 8;
        ts[k][tx] = W[(size_t)(k0 + k) * DIM + n0 + tx];
    }
    __syncthreads();
    #pragma unroll
    for (int r = 0; r < 4; r++) {
        int n = ty + r * 8;
        float v = ts[tx][n];                      // W[k0+tx][n0+n]
        __half h, l;
        split_f16(v, h, l);
        size_t o = (size_t)(n0 + n) * KTOT + k0 + tx;
        whi[o] = h;
        wlo[o] = l;
    }
}

// ---------------------------------------------------------------------------
// Tensor-core mixture GEMM via mma.sync (fp16 A + hi/lo B, 2 passes, fp32 acc).
// z-batched: blockIdx.z selects A (via aStride), weight slot, and output.
// 512 threads / 16 warps: 4(M) x 4(N) warp grid, 32x32 warp tile, 3 stages.
// ---------------------------------------------------------------------------
__global__ __launch_bounds__(512)
void circuit_gemm_tc(const __half* __restrict__ A,      // base, + z*aStride
                     size_t aStride,
                     const __half* __restrict__ WhiB,   // slot base (z-indexed)
                     const __half* __restrict__ WloB,
                     const float* __restrict__ wgt,     // [TOK, NEXP]
                     float* __restrict__ o0,
                     float* __restrict__ o1,
                     float* __restrict__ o2)
{
    extern __shared__ char smem[];
    __shared__ float swgt[128 * NEXP];
    const uint32_t sb = (uint32_t)__cvta_generic_to_shared(smem);
    int tid = threadIdx.x, lane = tid & 31, wid = tid >> 5;
    int bm = blockIdx.y * 128, bn = blockIdx.x * 128;
    int z  = blockIdx.z;
    const __half* AZ  = A + (size_t)z * aStride;
    const __half* Whi = WhiB + (size_t)z * WSZ;
    const __half* Wlo = WloB + (size_t)z * WSZ;
    float* out = (z == 0) ? o0 : (z == 1) ? o1 : o2;

    // ---- loader role: 4 threads per row, 16-k quarter each ----
    int r  = tid >> 2;                 // 0..127
    int kq = (tid & 3) * 16;           // k quarter
    const __half* ap   = AZ  + (size_t)(bm + r) * DIM + kq;
    const __half* bhip = Whi + (size_t)(bn + r) * KTOT + kq;
    const __half* blop = Wlo + (size_t)(bn + r) * KTOT + kq;
    const uint32_t rowoff = (uint32_t)(r * PAD + kq) * 2;

    auto load_chunk = [&](int c) {
        uint32_t st = sb + (uint32_t)(c % NSTAGE) * STAGE_BYTES;
        int k0 = c * BK;
        int d0 = k0 & (DIM - 1);
        #pragma unroll
        for (int ci = 0; ci < 2; ci++) {
            cp16(st + rowoff + ci * 16,                 ap   + d0 + ci * 8);
            cp16(st + MAT_BYTES + rowoff + ci * 16,     bhip + k0 + ci * 8);
            cp16(st + 2 * MAT_BYTES + rowoff + ci * 16, blop + k0 + ci * 8);
        }
        cp_commit();
    };

    // ---- compute role: 4(M) x 4(N) warp grid, 32x32 warp tile ----
    int wm = (wid >> 2) * 32;
    int wn = (wid & 3) * 32;
    int arow = lane & 15;
    int acol = (lane >> 4) * 8;
    int q    = lane >> 3, rl = lane & 7;
    int brow = wn + ((q >= 2) ? 8 : 0) + rl;
    int bcol = (q & 1) * 8;
    const uint32_t aOff = (uint32_t)((wm + arow) * PAD + acol) * 2;
    const uint32_t bOff = (uint32_t)MAT_BYTES + (uint32_t)(brow * PAD + bcol) * 2;
    int g = lane >> 2;

    float acc[2][4][4];
    float seg[2][4][4];
    #pragma unroll
    for (int i = 0; i < 2; i++)
        #pragma unroll
        for (int j = 0; j < 4; j++)
            #pragma unroll
            for (int e = 0; e < 4; e++) acc[i][j][e] = 0.f;

    // ---- prologue ----
    for (int idx = tid; idx < 128 * NEXP; idx += 512)
        swgt[idx] = wgt[(size_t)(bm + (idx >> 3)) * NEXP + (idx & 7)];
    load_chunk(0);
    load_chunk(1);

    int c = 0;
    for (int e = 0; e < NEXP; e++) {
        #pragma unroll
        for (int i = 0; i < 2; i++)
            #pragma unroll
            for (int j = 0; j < 4; j++)
                #pragma unroll
                for (int t = 0; t < 4; t++) seg[i][j][t] = 0.f;

        for (int dc = 0; dc < 16; dc++, c++) {
            if (c + 1 < NCHUNK) cp_wait<1>(); else cp_wait<0>();
            __syncthreads();
            if (c + 2 < NCHUNK) load_chunk(c + 2);

            uint32_t st = sb + (uint32_t)(c % NSTAGE) * STAGE_BYTES;
            uint32_t aHi = st + aOff;
            uint32_t bHi = st + bOff;

            #pragma unroll
            for (int ks = 0; ks < 4; ks++) {
                uint32_t kb = (uint32_t)(ks * 16) * 2;
                uint32_t bh[4][2], bl[4][2];
                #pragma unroll
                for (int p = 0; p < 2; p++) {
                    uint32_t ba = bHi + (uint32_t)(p * 16 * PAD) * 2 + kb;
                    LDSM4(bh[2*p][0], bh[2*p][1], bh[2*p+1][0], bh[2*p+1][1], ba);
                    LDSM4(bl[2*p][0], bl[2*p][1], bl[2*p+1][0], bl[2*p+1][1], ba + MAT_BYTES);
                }
                uint32_t ah[2][4];
                #pragma unroll
                for (int mt = 0; mt < 2; mt++) {
                    uint32_t aa = aHi + (uint32_t)(mt * 16 * PAD) * 2 + kb;
                    LDSM4(ah[mt][0], ah[mt][1], ah[mt][2], ah[mt][3], aa);
                }
                // pass-major: 8 independent accumulators between same-acc reuse
                #pragma unroll
                for (int mt = 0; mt < 2; mt++)
                    #pragma unroll
                    for (int nt = 0; nt < 4; nt++)
                        mma_f16(seg[mt][nt], ah[mt], bh[nt]);
                #pragma unroll
                for (int mt = 0; mt < 2; mt++)
                    #pragma unroll
                    for (int nt = 0; nt < 4; nt++)
                        mma_f16(seg[mt][nt], ah[mt], bl[nt]);
            }
        }

        // ---- expert boundary: acc += w(row, e) * seg ----
        #pragma unroll
        for (int mt = 0; mt < 2; mt++) {
            float w0 = swgt[(wm + mt * 16 + g) * NEXP + e];
            float w1 = swgt[(wm + mt * 16 + 8 + g) * NEXP + e];
            #pragma unroll
            for (int nt = 0; nt < 4; nt++) {
                acc[mt][nt][0] += w0 * seg[mt][nt][0];
                acc[mt][nt][1] += w0 * seg[mt][nt][1];
                acc[mt][nt][2] += w1 * seg[mt][nt][2];
                acc[mt][nt][3] += w1 * seg[mt][nt][3];
            }
        }
    }

    // ---- epilogue ----
    int tig = lane & 3;
    #pragma unroll
    for (int mt = 0; mt < 2; mt++) {
        #pragma unroll
        for (int nt = 0; nt < 4; nt++) {
            int row = bm + wm + mt * 16 + g;
            int col = bn + wn + nt * 8 + tig * 2;
            *(float2*)(out + (size_t)row * DIM + col) =
                make_float2(acc[mt][nt][0], acc[mt][nt][1]);
            *(float2*)(out + (size_t)(row + 8) * DIM + col) =
                make_float2(acc[mt][nt][2], acc[mt][nt][3]);
        }
    }
}

// ---------------------------------------------------------------------------
// Router + fused fp16 convert: 48 logits per token, softmax8 x2 + top-3,
// plus writes the token's activation row as fp16 (replaces split_kernel).
// ---------------------------------------------------------------------------
__global__ void router_kernel(const float* __restrict__ act,
                              const float* __restrict__ Wi,
                              const float* __restrict__ Wp,
                              const float* __restrict__ Wo,
                              float* __restrict__ inw,
                              int*   __restrict__ pidx,
                              float* __restrict__ outw,
                              __half* __restrict__ acth)   // fp16 copy out (or NULL)
{
    int t    = blockIdx.x;
    int tid  = threadIdx.x;
    int lane = tid & 31, warp = tid >> 5;
    __shared__ float xs[DIM];
    __shared__ float lg[48];

    const float* xr = act + (size_t)t * DIM;
    for (int i = tid; i < DIM; i += 128) xs[i] = xr[i];
    __syncthreads();

    // fused fp16 conversion of this token's row (identical rounding to split_kernel)
    if (acth) {
        __half* oh = acth + (size_t)t * DIM;
        #pragma unroll
        for (int rpt = 0; rpt < 2; rpt++) {
            int i = (tid + rpt * 128) * 4;
            __half h4[4];
            h4[0] = __float2half_rn(xs[i]);
            h4[1] = __float2half_rn(xs[i + 1]);
            h4[2] = __float2half_rn(xs[i + 2]);
            h4[3] = __float2half_rn(xs[i + 3]);
            *(uint64_t*)(oh + i) = *(uint64_t*)h4;
        }
    }

    for (int l = warp; l < 48; l += 4) {
        const float* wr = (l < 8) ? (Wi + (size_t)l * DIM)
                        : (l < 40) ? (Wp + (size_t)(l - 8) * DIM)
                                   : (Wo + (size_t)(l - 40) * DIM);
        float s = 0.f;
        for (int d = lane; d < DIM; d += 32) s += xs[d] * wr[d];
        #pragma unroll
        for (int off = 16; off > 0; off >>= 1)
            s += __shfl_xor_sync(0xffffffffu, s, off);
        if (lane == 0) lg[l] = s;
    }
    __syncthreads();

    if (tid == 0) {
        float m = lg[0];
        for (int i = 1; i < 8; i++) m = fmaxf(m, lg[i]);
        float e[8], sum = 0.f;
        for (int i = 0; i < 8; i++) { e[i] = expf(lg[i] - m); sum += e[i]; }
        for (int i = 0; i < 8; i++) inw[t * 8 + i] = e[i] / sum;

        bool used[NPROC];
        for (int n = 0; n < NPROC; n++) used[n] = false;
        for (int r = 0; r < TOPK; r++) {
            float best = -INFINITY; int bi = 0;
            for (int n = 0; n < NPROC; n++)
                if (!used[n] && lg[8 + n] > best) { best = lg[8 + n]; bi = n; }
            used[bi] = true;
            pidx[t * TOPK + r] = bi;
        }

        m = lg[40];
        for (int i = 1; i < 8; i++) m = fmaxf(m, lg[40 + i]);
        sum = 0.f;
        for (int i = 0; i < 8; i++) { e[i] = expf(lg[40 + i] - m); sum += e[i]; }
        for (int i = 0; i < 8; i++) outw[t * 8 + i] = e[i] / sum;
    }
}

// ---------------------------------------------------------------------------
// Householder reflections (z-batched): h -= 2 (h.v)/(v.v + 1e-8) v, 3x/token;
// writes fp16 output to slot z.
// ---------------------------------------------------------------------------
__global__ void householder_kernel(const float* __restrict__ hbase,
                                   const float* __restrict__ v0,
                                   const float* __restrict__ v1,
                                   const float* __restrict__ v2,
                                   const int* __restrict__ pidx,
                                   __half* __restrict__ outB)
{
    int t = blockIdx.x, tid = threadIdx.x;
    int z = blockIdx.y;
    int lane = tid & 31, warp = tid >> 5;
    const float* vproc = (z == 0) ? v0 : (z == 1) ? v1 : v2;
    const float* hr = hbase + ((size_t)z * TOK + t) * DIM;
    __half* oh = outB + ((size_t)z * TOK + t) * DIM;

    float hv[4];
    #pragma unroll
    for (int i = 0; i < 4; i++) hv[i] = hr[tid + 256 * i];

    __shared__ float sred[16];

    for (int rfl = 0; rfl < TOPK; rfl++) {
        int idx = pidx[t * TOPK + rfl];
        const float* v = vproc + (size_t)idx * DIM;
        float vr[4];
        float d1 = 0.f, d2 = 0.f;
        #pragma unroll
        for (int i = 0; i < 4; i++) {
            vr[i] = v[tid + 256 * i];
            d1 += hv[i] * vr[i];
            d2 += vr[i] * vr[i];
        }
        #pragma unroll
        for (int off = 16; off > 0; off >>= 1) {
            d1 += __shfl_xor_sync(0xffffffffu, d1, off);
            d2 += __shfl_xor_sync(0xffffffffu, d2, off);
        }
        if (lane == 0) { sred[warp] = d1; sred[8 + warp] = d2; }
        __syncthreads();
        float t1 = 0.f, t2 = 0.f;
        #pragma unroll
        for (int w = 0; w < 8; w++) { t1 += sred[w]; t2 += sred[8 + w]; }
        float f = 2.f * t1 / (t2 + 1e-8f);
        #pragma unroll
        for (int i = 0; i < 4; i++) hv[i] -= f * vr[i];
        __syncthreads();
    }

    #pragma unroll
    for (int i = 0; i < 4; i++)
        oh[tid + 256 * i] = __float2half_rn(hv[i]);
}

// ---------------------------------------------------------------------------
// Causal attention, online softmax (fp32). 32 q-rows per block (512 thr),
// 2 rows per warp sharing K/V smem reads; float4 staging; lane-per-key
// within 32-key batches. Also writes fp16 copy of O (replaces split(O)).
// Dynamic smem.
// ---------------------------------------------------------------------------
__global__ __launch_bounds__(512)
void attn_kernel(const float* __restrict__ Q,
                 const float* __restrict__ K,
                 const float* __restrict__ V,
                 float* __restrict__ O,
                 __half* __restrict__ Oh)
{
    extern __shared__ float asm_buf[];
    float* Ks = asm_buf + ATTN_KS_OFF;   // [32][KS_STRIDE]
    float* Vs = asm_buf + ATTN_VS_OFF;   // [32][KS_STRIDE]
    float* qs = asm_buf + ATTN_QS_OFF;   // [32][QS_STRIDE]

    const float scale = 0.08838834764831845f;  // 1/sqrt(128)
    int bh = blockIdx.y;
    int b = bh >> 3, hh = bh & 7;
    int q0 = blockIdx.x * 32;
    int tid = threadIdx.x, lane = tid & 31, warp = tid >> 5;

    const float* Qb = Q + (size_t)b * SEQ * DIM + hh * DHEAD;
    const float* Kb = K + (size_t)b * SEQ * DIM + hh * DHEAD;
    const float* Vb = V + (size_t)b * SEQ * DIM + hh * DHEAD;
    float*       Ob = O + (size_t)b * SEQ * DIM + hh * DHEAD;
    __half*      Oh2 = Oh + (size_t)b * SEQ * DIM + hh * DHEAD;

    int row0 = q0 + warp;
    int row1 = q0 + 16 + warp;

    for (int idx = tid; idx < 32 * 32; idx += 512) {
        int j = idx >> 5, d4 = idx & 31;
        ((float4*)&qs[j * QS_STRIDE])[d4] =
            ((const float4*)(Qb + (size_t)(q0 + j) * DIM))[d4];
    }

    float acc0[4] = {0.f, 0.f, 0.f, 0.f};
    float acc1[4] = {0.f, 0.f, 0.f, 0.f};
    float mi0 = -1e30f, li0 = 0.f;
    float mi1 = -1e30f, li1 = 0.f;

    int kend = q0 + 32;
    for (int c0 = 0; c0 < kend; c0 += 32) {
        __syncthreads();
        for (int idx = tid; idx < 32 * 32; idx += 512) {
            int j = idx >> 5, d4 = idx & 31;
            ((float4*)&Ks[j * KS_STRIDE])[d4] =
                ((const float4*)(Kb + (size_t)(c0 + j) * DIM))[d4];
            ((float4*)&Vs[j * KS_STRIDE])[d4] =
                ((const float4*)(Vb + (size_t)(c0 + j) * DIM))[d4];
        }
        __syncthreads();

        int kg = c0 + lane;
        const float4* kr  = (const float4*)&Ks[lane * KS_STRIDE];
        const float4* qr0 = (const float4*)&qs[warp * QS_STRIDE];
        const float4* qr1 = (const float4*)&qs[(warp + 16) * QS_STRIDE];
        float s0 = 0.f, s1 = 0.f;
        #pragma unroll
        for (int w = 0; w < 32; w++) {
            float4 kk = kr[w];
            float4 qa = qr0[w];
            float4 qb = qr1[w];
            s0 += qa.x * kk.x + qa.y * kk.y + qa.z * kk.z + qa.w * kk.w;
            s1 += qb.x * kk.x + qb.y * kk.y + qb.z * kk.z + qb.w * kk.w;
        }
        s0 *= scale;
        s1 *= scale;
        if (kg > row0) s0 = -1e30f;
        if (kg > row1) s1 = -1e30f;

        float mb0 = s0, mb1 = s1;
        #pragma unroll
        for (int off = 16; off > 0; off >>= 1) {
            mb0 = fmaxf(mb0, __shfl_xor_sync(0xffffffffu, mb0, off));
            mb1 = fmaxf(mb1, __shfl_xor_sync(0xffffffffu, mb1, off));
        }
        float mn0 = fmaxf(mi0, mb0);
        float mn1 = fmaxf(mi1, mb1);
        float cr0 = expf(mi0 - mn0);
        float cr1 = expf(mi1 - mn1);
        float p0 = expf(s0 - mn0);
        float p1 = expf(s1 - mn1);
        float ps0 = p0, ps1 = p1;
        #pragma unroll
        for (int off = 16; off > 0; off >>= 1) {
            ps0 += __shfl_xor_sync(0xffffffffu, ps0, off);
            ps1 += __shfl_xor_sync(0xffffffffu, ps1, off);
        }
        li0 = li0 * cr0 + ps0;
        li1 = li1 * cr1 + ps1;

        #pragma unroll
        for (int i = 0; i < 4; i++) { acc0[i] *= cr0; acc1[i] *= cr1; }
        #pragma unroll
        for (int j = 0; j < 32; j++) {
            float pj0 = __shfl_sync(0xffffffffu, p0, j);
            float pj1 = __shfl_sync(0xffffffffu, p1, j);
            float4 vv = *(const float4*)&Vs[j * KS_STRIDE + lane * 4];
            acc0[0] += pj0 * vv.x;  acc0[1] += pj0 * vv.y;
            acc0[2] += pj0 * vv.z;  acc0[3] += pj0 * vv.w;
            acc1[0] += pj1 * vv.x;  acc1[1] += pj1 * vv.y;
            acc1[2] += pj1 * vv.z;  acc1[3] += pj1 * vv.w;
        }
        mi0 = mn0;
        mi1 = mn1;
    }

    float inv0 = 1.f / li0;
    float inv1 = 1.f / li1;
    float4 o0 = make_float4(acc0[0] * inv0, acc0[1] * inv0, acc0[2] * inv0, acc0[3] * inv0);
    float4 o1 = make_float4(acc1[0] * inv1, acc1[1] * inv1, acc1[2] * inv1, acc1[3] * inv1);
    *(float4*)(Ob + (size_t)row0 * DIM + lane * 4) = o0;
    *(float4*)(Ob + (size_t)row1 * DIM + lane * 4) = o1;

    // fused fp16 copy (identical rounding to split_kernel)
    __half h0[4], h1[4];
    h0[0] = __float2half_rn(o0.x); h0[1] = __float2half_rn(o0.y);
    h0[2] = __float2half_rn(o0.z); h0[3] = __float2half_rn(o0.w);
    h1[0] = __float2half_rn(o1.x); h1[1] = __float2half_rn(o1.y);
    h1[2] = __float2half_rn(o1.z); h1[3] = __float2half_rn(o1.w);
    *(uint64_t*)(Oh2 + (size_t)row0 * DIM + lane * 4) = *(uint64_t*)h0;
    *(uint64_t*)(Oh2 + (size_t)row1 * DIM + lane * 4) = *(uint64_t*)h1;
}

// ---------------------------------------------------------------------------
// Launch
// ---------------------------------------------------------------------------
extern "C" void kernel_launch(void* const* d_in, const int* in_sizes, int n_in,
                              void* d_out, int out_size)
{
    const float* x       = (const float*)d_in[0];
    const float* Wr_in   = (const float*)d_in[2];
    const float* Wr_proc = (const float*)d_in[3];
    const float* Wr_out  = (const float*)d_in[4];
    const float* WrO_in  = (const float*)d_in[5];
    const float* WrO_proc= (const float*)d_in[6];
    const float* WrO_out = (const float*)d_in[7];
    const float* Wq_in   = (const float*)d_in[8];
    const float* vq      = (const float*)d_in[9];
    const float* Wq_out  = (const float*)d_in[10];
    const float* Wk_in   = (const float*)d_in[11];
    const float* vk      = (const float*)d_in[12];
    const float* Wk_out  = (const float*)d_in[13];
    const float* Wv_in   = (const float*)d_in[14];
    const float* vv      = (const float*)d_in[15];
    const float* Wv_out  = (const float*)d_in[16];
    const float* Wo_in   = (const float*)d_in[17];
    const float* vo      = (const float*)d_in[18];
    const float* Wo_out  = (const float*)d_in[19];
    float* out = (float*)d_out;

    float *h, *Q, *Kc, *V, *O, *inw, *outw;
    int* pidx;
    __half *whi, *wlo, *xh, *hh;
    cudaGetSymbolAddress((void**)&h,    g_h);
    cudaGetSymbolAddress((void**)&Q,    g_Q);
    cudaGetSymbolAddress((void**)&Kc,   g_Kc);
    cudaGetSymbolAddress((void**)&V,    g_V);
    cudaGetSymbolAddress((void**)&O,    g_O);
    cudaGetSymbolAddress((void**)&inw,  g_inw);
    cudaGetSymbolAddress((void**)&outw, g_outw);
    cudaGetSymbolAddress((void**)&pidx, g_pidx);
    cudaGetSymbolAddress((void**)&whi,  g_whi);
    cudaGetSymbolAddress((void**)&wlo,  g_wlo);
    cudaGetSymbolAddress((void**)&xh,   g_xh);
    cudaGetSymbolAddress((void**)&hh,   g_hh);

    cudaFuncSetAttribute(circuit_gemm_tc,
                         cudaFuncAttributeMaxDynamicSharedMemorySize,
                         SMEM_GEMM_BYTES);
    cudaFuncSetAttribute(attn_kernel,
                         cudaFuncAttributeMaxDynamicSharedMemorySize,
                         SMEM_ATTN_BYTES);

    dim3 gGemm3(DIM / 128, TOK / 128, 3);   // 768 CTAs
    dim3 gGemm1(DIM / 128, TOK / 128, 1);   // 256 CTAs
    dim3 gPrep8(DIM / 32, KTOT / 32, 8);    // all 8 weight slots, upfront

    // ---- All weight preps upfront (weights independent of activations) ----
    prep_w_kernel<<<gPrep8, 256>>>(Wq_in, Wk_in, Wv_in, Wq_out, Wk_out, Wv_out,
                                   Wo_in, Wo_out, whi, wlo);

    // ---- Router on x (+ fused fp16 convert of x) ----
    router_kernel<<<TOK, 128>>>(x, Wr_in, Wr_proc, Wr_out, inw, pidx, outw, xh);

    // ---- Q/K/V in-projections (slots 0-2) ----
    circuit_gemm_tc<<<gGemm3, 512, SMEM_GEMM_BYTES>>>(
        xh, 0, whi, wlo, inw, h, h + ASZ, h + 2 * ASZ);

    // ---- Householders (fused) ----
    householder_kernel<<<dim3(TOK, 3), 256>>>(h, vq, vk, vv, pidx, hh);

    // ---- Q/K/V out-projections (slots 3-5) ----
    circuit_gemm_tc<<<gGemm3, 512, SMEM_GEMM_BYTES>>>(
        hh, ASZ, whi + 3 * WSZ, wlo + 3 * WSZ, outw, Q, Kc, V);

    // ---- Attention (+ fused fp16 convert of O into xh) ----
    attn_kernel<<<dim3(SEQ / 32, NBATCH * NH), 512, SMEM_ATTN_BYTES>>>(Q, Kc, V, O, xh);

    // ---- Router on O + output circuit (slots 6, 7) ----
    router_kernel<<<TOK, 128>>>(O, WrO_in, WrO_proc, WrO_out, inw, pidx, outw,
                                (__half*)0);
    circuit_gemm_tc<<<gGemm1, 512, SMEM_GEMM_BYTES>>>(
        xh, 0, whi + 6 * WSZ, wlo + 6 * WSZ, inw, h, h, h);
    householder_kernel<<<dim3(TOK, 1), 256>>>(h, vo, vo, vo, pidx, hh);
    circuit_gemm_tc<<<gGemm1, 512, SMEM_GEMM_BYTES>>>(
        hh, 0, whi + 7 * WSZ, wlo + 7 * WSZ, outw, out, out, out);

    (void)in_sizes; (void)n_in; (void)out_size;
}